// round 16
// baseline (speedup 1.0000x reference)
#include <cuda_runtime.h>
#include <cuda_fp8.h>
#include <cuda_fp16.h>
#include <math_constants.h>
#include <cstdint>

#define SQ 4096
#define HD 64
#define NH 16
#define BM 128
#define BN 128
#define NT (SQ / BN)
#define KSTR 72            // K smem row stride in halves (144B: ldmatrix conflict-free)
#define VSTR 136           // V smem row stride in halves (272B: ldmatrix conflict-free)
#define KBYTES (BN * KSTR * 2)   // 18432
#define VBYTES (HD * VSTR * 2)   // 17408
#define SMEM_TOT (3 * KBYTES + 3 * VBYTES)  // 107520 (x2 CTAs = 215KB <= 228KB)

// raw e4m3 code values held exactly in fp16
__device__ __half g_q8[NH * SQ * HD];
__device__ __half g_k8[NH * SQ * HD];
__device__ __half g_v8t[NH * HD * SQ];   // transposed [h][d][s]

// ---------- helpers ----------
__device__ __forceinline__ uint32_t s2u(const void* p) {
    uint32_t a;
    asm("{ .reg .u64 t; cvta.to.shared.u64 t, %1; cvt.u32.u64 %0, t; }"
        : "=r"(a) : "l"(p));
    return a;
}
__device__ __forceinline__ void cpa16(uint32_t dst, const void* src) {
    asm volatile("cp.async.cg.shared.global [%0], [%1], 16;" :: "r"(dst), "l"(src));
}
#define CPC() asm volatile("cp.async.commit_group;" ::: "memory")
#define CPW1() asm volatile("cp.async.wait_group 1;" ::: "memory")

__device__ __forceinline__ void mma16816(float* c, const uint32_t* a,
                                         uint32_t b0, uint32_t b1) {
    asm volatile(
        "mma.sync.aligned.m16n8k16.row.col.f32.f16.f16.f32 "
        "{%0,%1,%2,%3}, {%4,%5,%6,%7}, {%8,%9}, {%0,%1,%2,%3};"
        : "+f"(c[0]), "+f"(c[1]), "+f"(c[2]), "+f"(c[3])
        : "r"(a[0]), "r"(a[1]), "r"(a[2]), "r"(a[3]), "r"(b0), "r"(b1));
}
__device__ __forceinline__ void ldm4(uint32_t* r, uint32_t addr) {
    asm volatile("ldmatrix.sync.aligned.m8n8.x4.shared.b16 {%0,%1,%2,%3}, [%4];"
                 : "=r"(r[0]), "=r"(r[1]), "=r"(r[2]), "=r"(r[3]) : "r"(addr));
}

// MUFU exp2 — same accuracy class (~2.4e-7) as the __expf that passed in R0
__device__ __forceinline__ float exp2p(float t) {
    float r;
    asm("ex2.approx.f32 %0, %1;" : "=f"(r) : "f"(t));
    return r;
}

// pair of floats -> e4m3 (satfinite RN-even, hardware) -> fp16 pair (exact)
__device__ __forceinline__ uint32_t q8pair(float x, float y) {
    __nv_fp8x2_storage_t b2 = __nv_cvt_float2_to_fp8x2(make_float2(x, y),
                                                       __NV_SATFINITE, __NV_E4M3);
    __half2_raw h2 = __nv_cvt_fp8x2_to_halfraw2(b2, __NV_E4M3);
    return *reinterpret_cast<const uint32_t*>(&h2);
}

// ---------- fused preprocessing: fp32 -> e4m3 codes in fp16 ----------
// grid.z: 0 -> quantize Q, 1 -> quantize K, 2 -> quantize+transpose V
__global__ void prep(const float4* __restrict__ qin, const float4* __restrict__ kin,
                     const float* __restrict__ vin,
                     uint32_t* __restrict__ qout, uint32_t* __restrict__ kout,
                     const float* __restrict__ sq_p, const float* __restrict__ sk_p,
                     const float* __restrict__ sv_p, int n4) {
    __shared__ __half t[64][66];
    if (blockIdx.z < 2) {
        int i = blockIdx.x * blockDim.x + threadIdx.x;
        if (i >= n4) return;
        const float4* in = blockIdx.z ? kin : qin;
        uint32_t* outp = blockIdx.z ? kout : qout;
        float inv = 1.0f / (blockIdx.z ? *sk_p : *sq_p);
        float4 v = in[i];
        outp[2 * i]     = q8pair(v.x * inv, v.y * inv);
        outp[2 * i + 1] = q8pair(v.z * inv, v.w * inv);
        return;
    }
    // V path: 1024 active blocks (x < 1024), 64-row transpose tiles
    if (blockIdx.x >= (SQ / 64) * NH) return;
    int h = blockIdx.x & (NH - 1), st = (blockIdx.x >> 4) * 64;
    float inv = 1.0f / *sv_p;
    int tid = threadIdx.x;
#pragma unroll
    for (int e = 0; e < 16; e++) {
        int lin = tid + e * 256;
        int sr = lin >> 6, d = lin & 63;
        uint32_t pr = q8pair(vin[((size_t)h * SQ + st + sr) * HD + d] * inv, 0.0f);
        t[sr][d] = *reinterpret_cast<const __half*>(&pr);
    }
    __syncthreads();
#pragma unroll
    for (int e = 0; e < 16; e++) {
        int lin = tid + e * 256;
        int d = lin >> 6, sc = lin & 63;
        g_v8t[((size_t)h * HD + d) * SQ + st + sc] = t[sc][d];
    }
}

// ---- shared macros ----
#define PFK(t, b) do {                                                        \
        const __half* src = Kp + (size_t)(t) * BN * HD;                       \
        uint32_t db = sb + (b) * KBYTES;                                      \
        _Pragma("unroll")                                                     \
        for (int i_ = 0; i_ < 4; i_++) {                                      \
            int idx = tid + i_ * 256; int row = idx >> 3, seg = idx & 7;      \
            cpa16(db + row * (KSTR * 2) + seg * 16, src + row * HD + seg * 8);\
        } } while (0)
#define PFV(t, b) do {                                                        \
        uint32_t db = sb + 3 * KBYTES + (b) * VBYTES;                         \
        _Pragma("unroll")                                                     \
        for (int i_ = 0; i_ < 4; i_++) {                                      \
            int idx = tid + i_ * 256; int d = idx >> 4, seg = idx & 15;       \
            cpa16(db + d * (VSTR * 2) + seg * 16,                             \
                  Vp + (size_t)d * SQ + (t) * BN + seg * 8);                  \
        } } while (0)
// pass-2 QK block (register-tight: load/mma interleaved, unchanged from R14)
#define QKBLK(sc, kbuf, q) do {                                               \
        _Pragma("unroll")                                                     \
        for (int jj_ = 0; jj_ < 4; jj_++) {                                   \
            sc[jj_][0] = sc[jj_][1] = sc[jj_][2] = sc[jj_][3] = 0.0f;         \
            uint32_t ad_ = (kbuf) + kq_lane +                                 \
                           (uint32_t)(((q) * 4 + jj_) * 8) * (KSTR * 2);      \
            uint32_t f0_[4], f1_[4];                                          \
            ldm4(f0_, ad_); ldm4(f1_, ad_ + 64);                              \
            mma16816(sc[jj_], qa[0], f0_[0], f0_[1]);                         \
            mma16816(sc[jj_], qa[1], f0_[2], f0_[3]);                         \
            mma16816(sc[jj_], qa[2], f1_[0], f1_[1]);                         \
            mma16816(sc[jj_], qa[3], f1_[2], f1_[3]);                         \
        } } while (0)
// pass-1 QK block (reg headroom: ALL 8 ldm4 issued up front -> 8-deep LDSM MLP,
// then 16 MMAs as one burst; bit-identical math to QKBLK)
#define QKBLK_P1(sc, kbuf, q) do {                                            \
        uint32_t F_[8][4];                                                    \
        _Pragma("unroll")                                                     \
        for (int jj_ = 0; jj_ < 4; jj_++) {                                   \
            uint32_t ad_ = (kbuf) + kq_lane +                                 \
                           (uint32_t)(((q) * 4 + jj_) * 8) * (KSTR * 2);      \
            ldm4(F_[2 * jj_], ad_); ldm4(F_[2 * jj_ + 1], ad_ + 64);          \
        }                                                                     \
        _Pragma("unroll")                                                     \
        for (int jj_ = 0; jj_ < 4; jj_++) {                                   \
            sc[jj_][0] = sc[jj_][1] = sc[jj_][2] = sc[jj_][3] = 0.0f;         \
            mma16816(sc[jj_], qa[0], F_[2 * jj_][0], F_[2 * jj_][1]);         \
            mma16816(sc[jj_], qa[1], F_[2 * jj_][2], F_[2 * jj_][3]);         \
            mma16816(sc[jj_], qa[2], F_[2 * jj_ + 1][0], F_[2 * jj_ + 1][1]); \
            mma16816(sc[jj_], qa[3], F_[2 * jj_ + 1][2], F_[2 * jj_ + 1][3]); \
        } } while (0)
#define SUMBLK(sc) do {                                                       \
        float a0_ = 0.0f, a1_ = 0.0f;                                         \
        _Pragma("unroll")                                                     \
        for (int jj_ = 0; jj_ < 4; jj_++) {                                   \
            a0_ += exp2p(sc[jj_][0] * qs2) + exp2p(sc[jj_][1] * qs2);         \
            a1_ += exp2p(sc[jj_][2] * qs2) + exp2p(sc[jj_][3] * qs2);         \
        }                                                                     \
        l0 += a0_;                                                            \
        l1 += a1_;                                                            \
    } while (0)
#define PVQ(sc, q) do {                                                       \
        uint32_t pa[2][4];                                                    \
        _Pragma("unroll")                                                     \
        for (int c_ = 0; c_ < 2; c_++) {                                      \
            _Pragma("unroll")                                                 \
            for (int hf_ = 0; hf_ < 2; hf_++) {                               \
                const float* s4_ = sc[2 * c_ + hf_];                          \
                float e00_ = exp2p(fmaf(s4_[0], qs2, C0));                    \
                float e01_ = exp2p(fmaf(s4_[1], qs2, C0));                    \
                float e10_ = exp2p(fmaf(s4_[2], qs2, C1));                    \
                float e11_ = exp2p(fmaf(s4_[3], qs2, C1));                    \
                pa[c_][2 * hf_ + 0] = q8pair(e00_, e01_);                     \
                pa[c_][2 * hf_ + 1] = q8pair(e10_, e11_);                     \
            }                                                                 \
        }                                                                     \
        _Pragma("unroll")                                                     \
        for (int dt_ = 0; dt_ < 8; dt_++) {                                   \
            uint32_t av_ = vbuf + v_lane + (uint32_t)(dt_ * 8) * (VSTR * 2) + \
                           (uint32_t)((q) * 64);                              \
            uint32_t g_[4];                                                   \
            ldm4(g_, av_);                                                    \
            mma16816(oacc[dt_], pa[0], g_[0], g_[1]);                         \
            mma16816(oacc[dt_], pa[1], g_[2], g_[3]);                         \
        } } while (0)

// ---------- fused attention: pass 1 (sumexp) + pass 2 (quantized probs + PV) ----------
__global__ __launch_bounds__(256, 2) void attn_kernel(
    const float* __restrict__ sq_p, const float* __restrict__ sk_p,
    const float* __restrict__ sv_p, const float* __restrict__ dsc_p,
    const float* __restrict__ osc_p, float* __restrict__ out) {
    extern __shared__ char smc[];
    const uint32_t sb = s2u(smc);
    const int tid = threadIdx.x;
    const int w = tid >> 5, l = tid & 31;
    const int qr = l >> 2, qc = l & 3;
    const int h = blockIdx.y, s0 = blockIdx.x * BM;
    const int wodd = w & 1;   // odd warps sweep q-blocks in reverse (phase stagger)

    const float sqv = __ldg(sq_p), skv = __ldg(sk_p), svv = __ldg(sv_p);
    const float dsc = __ldg(dsc_p), osc = __ldg(osc_p);
    const float qs2 = sqv * skv * 0.125f * 1.4426950408889634f;

    // per-lane ldmatrix base offsets (matrix = l>>3, row-in-matrix = l&7)
    const uint32_t kq_lane = (uint32_t)(l & 7) * (KSTR * 2) + (uint32_t)(l >> 3) * 16;
    const uint32_t v_lane  = (uint32_t)(l & 7) * (VSTR * 2) + (uint32_t)(l >> 3) * 16;

    const __half* Qp = g_q8 + ((size_t)h * SQ + s0 + w * 16) * HD;
    const __half* Kp = g_k8 + (size_t)h * SQ * HD;
    const __half* Vp = g_v8t + (size_t)h * HD * SQ;

    // Q fragments: 16 rows x 64 cols per warp, resident in registers
    uint32_t qa[4][4];
#pragma unroll
    for (int kc = 0; kc < 4; kc++) {
        qa[kc][0] = *(const uint32_t*)(Qp + (size_t)qr * HD + kc * 16 + qc * 2);
        qa[kc][1] = *(const uint32_t*)(Qp + (size_t)(qr + 8) * HD + kc * 16 + qc * 2);
        qa[kc][2] = *(const uint32_t*)(Qp + (size_t)qr * HD + kc * 16 + 8 + qc * 2);
        qa[kc][3] = *(const uint32_t*)(Qp + (size_t)(qr + 8) * HD + kc * 16 + 8 + qc * 2);
    }

    // fixed reference point m = 0 (arg = s*qs2, |arg|max ~ 8.5 << 127: safe)
    float l0 = 0.0f, l1 = 0.0f;

    // ================= PASS 1: row sumexp (triple-buffered K) =================
    PFK(0, 0); CPC();
    for (int t = 0; t < NT; t++) {
        if (t + 1 < NT) PFK(t + 1, (t + 1) % 3);
        CPC(); CPW1();
        __syncthreads();   // single barrier per iter: buf t%3 safe (last read t-2)
        const uint32_t kbuf = sb + (uint32_t)(t % 3) * KBYTES;
#pragma unroll
        for (int qi = 0; qi < 4; qi++) {
            const int q = wodd ? (3 - qi) : qi;
            float sc[4][4];
            QKBLK_P1(sc, kbuf, q);
            SUMBLK(sc);
        }
    }

    // sum across the 4 lanes of each row group
    l0 += __shfl_xor_sync(0xffffffffu, l0, 1);
    l0 += __shfl_xor_sync(0xffffffffu, l0, 2);
    l1 += __shfl_xor_sync(0xffffffffu, l1, 1);
    l1 += __shfl_xor_sync(0xffffffffu, l1, 2);
    // p/dsc = 2^(S*qs2 + C);  C = -log2(l*dsc)
    const float C0 = -__log2f(l0 * dsc);
    const float C1 = -__log2f(l1 * dsc);

    float oacc[8][4];
#pragma unroll
    for (int i = 0; i < 8; i++)
#pragma unroll
        for (int j = 0; j < 4; j++) oacc[i][j] = 0.0f;

    __syncthreads();   // all pass-1 reads of K buf 0 done before pass-2 overwrites it

    // ================= PASS 2: quantized probs + PV (triple-buffered) =================
    PFK(0, 0); PFV(0, 0); CPC();
    for (int t = 0; t < NT; t++) {
        if (t + 1 < NT) { PFK(t + 1, (t + 1) % 3); PFV(t + 1, (t + 1) % 3); }
        CPC(); CPW1();
        __syncthreads();
        const uint32_t kbuf = sb + (uint32_t)(t % 3) * KBYTES;
        const uint32_t vbuf = sb + 3 * KBYTES + (uint32_t)(t % 3) * VBYTES;
#pragma unroll
        for (int qi = 0; qi < 4; qi++) {
            const int q = wodd ? (3 - qi) : qi;
            float sc[4][4];
            QKBLK(sc, kbuf, q);
            PVQ(sc, q);
        }
    }

    // ---- epilogue: fp8 round-trip of O (hardware cvt), fp32 store ----
    const float pvi = dsc * svv / osc;
    float* Ob = out + ((size_t)h * SQ + s0 + w * 16) * HD;
#pragma unroll
    for (int dt = 0; dt < 8; dt++) {
        uint32_t h0 = q8pair(oacc[dt][0] * pvi, oacc[dt][1] * pvi);
        uint32_t h1 = q8pair(oacc[dt][2] * pvi, oacc[dt][3] * pvi);
        __half2 hh0 = *reinterpret_cast<const __half2*>(&h0);
        __half2 hh1 = *reinterpret_cast<const __half2*>(&h1);
        float2 f0 = __half22float2(hh0);
        float2 f1 = __half22float2(hh1);
        float2 r0v = make_float2(f0.x * osc, f0.y * osc);
        float2 r1v = make_float2(f1.x * osc, f1.y * osc);
        *(float2*)(Ob + (size_t)qr * HD + dt * 8 + qc * 2) = r0v;
        *(float2*)(Ob + (size_t)(qr + 8) * HD + dt * 8 + qc * 2) = r1v;
    }
}

extern "C" void kernel_launch(void* const* d_in, const int* in_sizes, int n_in,
                              void* d_out, int out_size) {
    const float* q = (const float*)d_in[0];
    const float* k = (const float*)d_in[1];
    const float* v = (const float*)d_in[2];
    const float* scale_q = (const float*)d_in[3];
    const float* scale_k = (const float*)d_in[4];
    const float* scale_v = (const float*)d_in[5];
    const float* descale_amax = (const float*)d_in[6];
    const float* out_scale = (const float*)d_in[7];
    float* out = (float*)d_out;

    void *qp, *kp;
    cudaGetSymbolAddress(&qp, g_q8);
    cudaGetSymbolAddress(&kp, g_k8);

    const int n4 = NH * SQ * HD / 4;
    prep<<<dim3(n4 / 256, 1, 3), 256>>>((const float4*)q, (const float4*)k, v,
                                        (uint32_t*)qp, (uint32_t*)kp,
                                        scale_q, scale_k, scale_v, n4);

    cudaFuncSetAttribute(attn_kernel, cudaFuncAttributeMaxDynamicSharedMemorySize,
                         SMEM_TOT);
    attn_kernel<<<dim3(SQ / BM, NH), 256, SMEM_TOT>>>(scale_q, scale_k, scale_v,
                                                      descale_amax, out_scale, out);
}

// round 17
// speedup vs baseline: 1.0394x; 1.0394x over previous
#include <cuda_runtime.h>
#include <cuda_fp8.h>
#include <cuda_fp16.h>
#include <math_constants.h>
#include <cstdint>

#define SQ 4096
#define HD 64
#define NH 16
#define BM 256             // q-rows per CTA (pass 2 handles 128-row halves)
#define BN 128
#define NT (SQ / BN)
#define KSTR 72            // K smem row stride in halves (144B: ldmatrix conflict-free)
#define VSTR 136           // V smem row stride in halves (272B: ldmatrix conflict-free)
#define KBYTES (BN * KSTR * 2)   // 18432
#define VBYTES (HD * VSTR * 2)   // 17408
#define SMEM_ML (3 * KBYTES + 3 * VBYTES)   // 107520: row-sum exchange array
#define SMEM_ALL (SMEM_ML + BM * 4)         // 108544 (x2 CTAs = 217KB <= 228KB)

// raw e4m3 code values held exactly in fp16
__device__ __half g_q8[NH * SQ * HD];
__device__ __half g_k8[NH * SQ * HD];
__device__ __half g_v8t[NH * HD * SQ];   // transposed [h][d][s]

// ---------- helpers ----------
__device__ __forceinline__ uint32_t s2u(const void* p) {
    uint32_t a;
    asm("{ .reg .u64 t; cvta.to.shared.u64 t, %1; cvt.u32.u64 %0, t; }"
        : "=r"(a) : "l"(p));
    return a;
}
__device__ __forceinline__ void cpa16(uint32_t dst, const void* src) {
    asm volatile("cp.async.cg.shared.global [%0], [%1], 16;" :: "r"(dst), "l"(src));
}
#define CPC() asm volatile("cp.async.commit_group;" ::: "memory")
#define CPW1() asm volatile("cp.async.wait_group 1;" ::: "memory")

__device__ __forceinline__ void mma16816(float* c, const uint32_t* a,
                                         uint32_t b0, uint32_t b1) {
    asm volatile(
        "mma.sync.aligned.m16n8k16.row.col.f32.f16.f16.f32 "
        "{%0,%1,%2,%3}, {%4,%5,%6,%7}, {%8,%9}, {%0,%1,%2,%3};"
        : "+f"(c[0]), "+f"(c[1]), "+f"(c[2]), "+f"(c[3])
        : "r"(a[0]), "r"(a[1]), "r"(a[2]), "r"(a[3]), "r"(b0), "r"(b1));
}
__device__ __forceinline__ void ldm4(uint32_t* r, uint32_t addr) {
    asm volatile("ldmatrix.sync.aligned.m8n8.x4.shared.b16 {%0,%1,%2,%3}, [%4];"
                 : "=r"(r[0]), "=r"(r[1]), "=r"(r[2]), "=r"(r[3]) : "r"(addr));
}

// MUFU exp2 — same accuracy class (~2.4e-7) as the __expf that passed in R0
__device__ __forceinline__ float exp2p(float t) {
    float r;
    asm("ex2.approx.f32 %0, %1;" : "=f"(r) : "f"(t));
    return r;
}

// pair of floats -> e4m3 (satfinite RN-even, hardware) -> fp16 pair (exact)
__device__ __forceinline__ uint32_t q8pair(float x, float y) {
    __nv_fp8x2_storage_t b2 = __nv_cvt_float2_to_fp8x2(make_float2(x, y),
                                                       __NV_SATFINITE, __NV_E4M3);
    __half2_raw h2 = __nv_cvt_fp8x2_to_halfraw2(b2, __NV_E4M3);
    return *reinterpret_cast<const uint32_t*>(&h2);
}

// ---------- fused preprocessing: fp32 -> e4m3 codes in fp16 ----------
// grid.z: 0 -> quantize Q, 1 -> quantize K, 2 -> quantize+transpose V
__global__ void prep(const float4* __restrict__ qin, const float4* __restrict__ kin,
                     const float* __restrict__ vin,
                     uint32_t* __restrict__ qout, uint32_t* __restrict__ kout,
                     const float* __restrict__ sq_p, const float* __restrict__ sk_p,
                     const float* __restrict__ sv_p, int n4) {
    __shared__ __half t[64][66];
    if (blockIdx.z < 2) {
        int i = blockIdx.x * blockDim.x + threadIdx.x;
        if (i >= n4) return;
        const float4* in = blockIdx.z ? kin : qin;
        uint32_t* outp = blockIdx.z ? kout : qout;
        float inv = 1.0f / (blockIdx.z ? *sk_p : *sq_p);
        float4 v = in[i];
        outp[2 * i]     = q8pair(v.x * inv, v.y * inv);
        outp[2 * i + 1] = q8pair(v.z * inv, v.w * inv);
        return;
    }
    if (blockIdx.x >= (SQ / 64) * NH) return;
    int h = blockIdx.x & (NH - 1), st = (blockIdx.x >> 4) * 64;
    float inv = 1.0f / *sv_p;
    int tid = threadIdx.x;
#pragma unroll
    for (int e = 0; e < 16; e++) {
        int lin = tid + e * 256;
        int sr = lin >> 6, d = lin & 63;
        uint32_t pr = q8pair(vin[((size_t)h * SQ + st + sr) * HD + d] * inv, 0.0f);
        t[sr][d] = *reinterpret_cast<const __half*>(&pr);
    }
    __syncthreads();
#pragma unroll
    for (int e = 0; e < 16; e++) {
        int lin = tid + e * 256;
        int d = lin >> 6, sc = lin & 63;
        g_v8t[((size_t)h * HD + d) * SQ + st + sc] = t[sc][d];
    }
}

// ---- shared macros ----
#define PFK(t, b) do {                                                        \
        const __half* src = Kp + (size_t)(t) * BN * HD;                       \
        uint32_t db = sb + (b) * KBYTES;                                      \
        _Pragma("unroll")                                                     \
        for (int i_ = 0; i_ < 4; i_++) {                                      \
            int idx = tid + i_ * 256; int row = idx >> 3, seg = idx & 7;      \
            cpa16(db + row * (KSTR * 2) + seg * 16, src + row * HD + seg * 8);\
        } } while (0)
#define PFV(t, b) do {                                                        \
        uint32_t db = sb + 3 * KBYTES + (b) * VBYTES;                         \
        _Pragma("unroll")                                                     \
        for (int i_ = 0; i_ < 4; i_++) {                                      \
            int idx = tid + i_ * 256; int d = idx >> 4, seg = idx & 15;       \
            cpa16(db + d * (VSTR * 2) + seg * 16,                             \
                  Vp + (size_t)d * SQ + (t) * BN + seg * 8);                  \
        } } while (0)
// pass-2 QK block (16 rows): load/mma interleaved (register-tight)
#define QKBLK(sc, kbuf, q) do {                                               \
        _Pragma("unroll")                                                     \
        for (int jj_ = 0; jj_ < 4; jj_++) {                                   \
            sc[jj_][0] = sc[jj_][1] = sc[jj_][2] = sc[jj_][3] = 0.0f;         \
            uint32_t ad_ = (kbuf) + kq_lane +                                 \
                           (uint32_t)(((q) * 4 + jj_) * 8) * (KSTR * 2);      \
            uint32_t f0_[4], f1_[4];                                          \
            ldm4(f0_, ad_); ldm4(f1_, ad_ + 64);                              \
            mma16816(sc[jj_], qa[0], f0_[0], f0_[1]);                         \
            mma16816(sc[jj_], qa[1], f0_[2], f0_[3]);                         \
            mma16816(sc[jj_], qa[2], f1_[0], f1_[1]);                         \
            mma16816(sc[jj_], qa[3], f1_[2], f1_[3]);                         \
        } } while (0)
// pass-1 sum of one 16-row x 32-key score block into lA/lB
#define SUMBLK2(sc, lA, lB) do {                                              \
        float a0_ = 0.0f, a1_ = 0.0f;                                         \
        _Pragma("unroll")                                                     \
        for (int jj_ = 0; jj_ < 4; jj_++) {                                   \
            a0_ += exp2p(sc[jj_][0] * qs2) + exp2p(sc[jj_][1] * qs2);         \
            a1_ += exp2p(sc[jj_][2] * qs2) + exp2p(sc[jj_][3] * qs2);         \
        }                                                                     \
        lA += a0_;                                                            \
        lB += a1_;                                                            \
    } while (0)
// pass-1 QK block: 32 rows (2 m-tiles) reuse ONE set of K fragments
#define QKBLK2(kbuf, q) do {                                                  \
        uint32_t F_[8][4];                                                    \
        _Pragma("unroll")                                                     \
        for (int jj_ = 0; jj_ < 4; jj_++) {                                   \
            uint32_t ad_ = (kbuf) + kq_lane +                                 \
                           (uint32_t)(((q) * 4 + jj_) * 8) * (KSTR * 2);      \
            ldm4(F_[2 * jj_], ad_); ldm4(F_[2 * jj_ + 1], ad_ + 64);          \
        }                                                                     \
        _Pragma("unroll")                                                     \
        for (int mt_ = 0; mt_ < 2; mt_++) {                                   \
            float sc[4][4];                                                   \
            _Pragma("unroll")                                                 \
            for (int jj_ = 0; jj_ < 4; jj_++) {                               \
                sc[jj_][0] = sc[jj_][1] = sc[jj_][2] = sc[jj_][3] = 0.0f;     \
                mma16816(sc[jj_], qa2[mt_][0], F_[2 * jj_][0], F_[2 * jj_][1]);\
                mma16816(sc[jj_], qa2[mt_][1], F_[2 * jj_][2], F_[2 * jj_][3]);\
                mma16816(sc[jj_], qa2[mt_][2], F_[2 * jj_ + 1][0], F_[2 * jj_ + 1][1]);\
                mma16816(sc[jj_], qa2[mt_][3], F_[2 * jj_ + 1][2], F_[2 * jj_ + 1][3]);\
            }                                                                 \
            SUMBLK2(sc, lacc[2 * mt_], lacc[2 * mt_ + 1]);                    \
        } } while (0)
#define PVQ(sc, q) do {                                                       \
        uint32_t pa[2][4];                                                    \
        _Pragma("unroll")                                                     \
        for (int c_ = 0; c_ < 2; c_++) {                                      \
            _Pragma("unroll")                                                 \
            for (int hf_ = 0; hf_ < 2; hf_++) {                               \
                const float* s4_ = sc[2 * c_ + hf_];                          \
                float e00_ = exp2p(fmaf(s4_[0], qs2, C0));                    \
                float e01_ = exp2p(fmaf(s4_[1], qs2, C0));                    \
                float e10_ = exp2p(fmaf(s4_[2], qs2, C1));                    \
                float e11_ = exp2p(fmaf(s4_[3], qs2, C1));                    \
                pa[c_][2 * hf_ + 0] = q8pair(e00_, e01_);                     \
                pa[c_][2 * hf_ + 1] = q8pair(e10_, e11_);                     \
            }                                                                 \
        }                                                                     \
        _Pragma("unroll")                                                     \
        for (int dt_ = 0; dt_ < 8; dt_++) {                                   \
            uint32_t av_ = vbuf + v_lane + (uint32_t)(dt_ * 8) * (VSTR * 2) + \
                           (uint32_t)((q) * 64);                              \
            uint32_t g_[4];                                                   \
            ldm4(g_, av_);                                                    \
            mma16816(oacc[dt_], pa[0], g_[0], g_[1]);                         \
            mma16816(oacc[dt_], pa[1], g_[2], g_[3]);                         \
        } } while (0)

// ---------- fused attention ----------
__global__ __launch_bounds__(256, 2) void attn_kernel(
    const float* __restrict__ sq_p, const float* __restrict__ sk_p,
    const float* __restrict__ sv_p, const float* __restrict__ dsc_p,
    const float* __restrict__ osc_p, float* __restrict__ out) {
    extern __shared__ char smc[];
    const uint32_t sb = s2u(smc);
    const int tid = threadIdx.x;
    const int w = tid >> 5, l = tid & 31;
    const int qr = l >> 2, qc = l & 3;
    const int h = blockIdx.y, s0 = blockIdx.x * BM;
    const int wodd = w & 1;

    const float sqv = __ldg(sq_p), skv = __ldg(sk_p), svv = __ldg(sv_p);
    const float dsc = __ldg(dsc_p), osc = __ldg(osc_p);
    const float qs2 = sqv * skv * 0.125f * 1.4426950408889634f;

    const uint32_t kq_lane = (uint32_t)(l & 7) * (KSTR * 2) + (uint32_t)(l >> 3) * 16;
    const uint32_t v_lane  = (uint32_t)(l & 7) * (VSTR * 2) + (uint32_t)(l >> 3) * 16;

    const __half* Kp = g_k8 + (size_t)h * SQ * HD;
    const __half* Vp = g_v8t + (size_t)h * HD * SQ;
    float* ml = (float*)(smc + SMEM_ML);

    // ===== PASS 1: row sumexp; warp owns 32 rows, K frags reused across 2 m-tiles
    {
        const __half* Qp1 = g_q8 + ((size_t)h * SQ + s0 + w * 32) * HD;
        uint32_t qa2[2][4][4];
#pragma unroll
        for (int mt = 0; mt < 2; mt++)
#pragma unroll
            for (int kc = 0; kc < 4; kc++) {
                const __half* Qm = Qp1 + (size_t)mt * 16 * HD;
                qa2[mt][kc][0] = *(const uint32_t*)(Qm + (size_t)qr * HD + kc * 16 + qc * 2);
                qa2[mt][kc][1] = *(const uint32_t*)(Qm + (size_t)(qr + 8) * HD + kc * 16 + qc * 2);
                qa2[mt][kc][2] = *(const uint32_t*)(Qm + (size_t)qr * HD + kc * 16 + 8 + qc * 2);
                qa2[mt][kc][3] = *(const uint32_t*)(Qm + (size_t)(qr + 8) * HD + kc * 16 + 8 + qc * 2);
            }

        float lacc[4] = {0.0f, 0.0f, 0.0f, 0.0f};
        PFK(0, 0); CPC();
        for (int t = 0; t < NT; t++) {
            if (t + 1 < NT) PFK(t + 1, (t + 1) % 3);
            CPC(); CPW1();
            __syncthreads();
            const uint32_t kbuf = sb + (uint32_t)(t % 3) * KBYTES;
#pragma unroll
            for (int qi = 0; qi < 4; qi++) {
                const int q = wodd ? (3 - qi) : qi;
                QKBLK2(kbuf, q);
            }
        }
#pragma unroll
        for (int i = 0; i < 4; i++) {
            lacc[i] += __shfl_xor_sync(0xffffffffu, lacc[i], 1);
            lacc[i] += __shfl_xor_sync(0xffffffffu, lacc[i], 2);
        }
        if (qc == 0) {
            ml[w * 32 + qr]      = lacc[0];
            ml[w * 32 + qr + 8]  = lacc[1];
            ml[w * 32 + qr + 16] = lacc[2];
            ml[w * 32 + qr + 24] = lacc[3];
        }
        __syncthreads();
    }

    // ===== PASS 2: two 128-row sub-passes (register-tight pass-2 layout)
    for (int hh = 0; hh < 2; hh++) {
        const int r0 = hh * 128 + w * 16;
        const __half* Qp = g_q8 + ((size_t)h * SQ + s0 + r0) * HD;
        uint32_t qa[4][4];
#pragma unroll
        for (int kc = 0; kc < 4; kc++) {
            qa[kc][0] = *(const uint32_t*)(Qp + (size_t)qr * HD + kc * 16 + qc * 2);
            qa[kc][1] = *(const uint32_t*)(Qp + (size_t)(qr + 8) * HD + kc * 16 + qc * 2);
            qa[kc][2] = *(const uint32_t*)(Qp + (size_t)qr * HD + kc * 16 + 8 + qc * 2);
            qa[kc][3] = *(const uint32_t*)(Qp + (size_t)(qr + 8) * HD + kc * 16 + 8 + qc * 2);
        }
        const float C0 = -__log2f(ml[r0 + qr] * dsc);
        const float C1 = -__log2f(ml[r0 + qr + 8] * dsc);

        float oacc[8][4];
#pragma unroll
        for (int i = 0; i < 8; i++)
#pragma unroll
            for (int j = 0; j < 4; j++) oacc[i][j] = 0.0f;

        PFK(0, 0); PFV(0, 0); CPC();
        for (int t = 0; t < NT; t++) {
            if (t + 1 < NT) { PFK(t + 1, (t + 1) % 3); PFV(t + 1, (t + 1) % 3); }
            CPC(); CPW1();
            __syncthreads();
            const uint32_t kbuf = sb + (uint32_t)(t % 3) * KBYTES;
            const uint32_t vbuf = sb + 3 * KBYTES + (uint32_t)(t % 3) * VBYTES;
#pragma unroll
            for (int qi = 0; qi < 4; qi++) {
                const int q = wodd ? (3 - qi) : qi;
                float sc[4][4];
                QKBLK(sc, kbuf, q);
                PVQ(sc, q);
            }
        }

        // epilogue: fp8 round-trip of O (hardware cvt), fp32 store
        const float pvi = dsc * svv / osc;
        float* Ob = out + ((size_t)h * SQ + s0 + r0) * HD;
#pragma unroll
        for (int dt = 0; dt < 8; dt++) {
            uint32_t h0 = q8pair(oacc[dt][0] * pvi, oacc[dt][1] * pvi);
            uint32_t h1 = q8pair(oacc[dt][2] * pvi, oacc[dt][3] * pvi);
            __half2 hh0 = *reinterpret_cast<const __half2*>(&h0);
            __half2 hh1 = *reinterpret_cast<const __half2*>(&h1);
            float2 f0 = __half22float2(hh0);
            float2 f1 = __half22float2(hh1);
            float2 r0v = make_float2(f0.x * osc, f0.y * osc);
            float2 r1v = make_float2(f1.x * osc, f1.y * osc);
            *(float2*)(Ob + (size_t)qr * HD + dt * 8 + qc * 2) = r0v;
            *(float2*)(Ob + (size_t)(qr + 8) * HD + dt * 8 + qc * 2) = r1v;
        }
    }
}

extern "C" void kernel_launch(void* const* d_in, const int* in_sizes, int n_in,
                              void* d_out, int out_size) {
    const float* q = (const float*)d_in[0];
    const float* k = (const float*)d_in[1];
    const float* v = (const float*)d_in[2];
    const float* scale_q = (const float*)d_in[3];
    const float* scale_k = (const float*)d_in[4];
    const float* scale_v = (const float*)d_in[5];
    const float* descale_amax = (const float*)d_in[6];
    const float* out_scale = (const float*)d_in[7];
    float* out = (float*)d_out;

    void *qp, *kp;
    cudaGetSymbolAddress(&qp, g_q8);
    cudaGetSymbolAddress(&kp, g_k8);

    const int n4 = NH * SQ * HD / 4;
    prep<<<dim3(n4 / 256, 1, 3), 256>>>((const float4*)q, (const float4*)k, v,
                                        (uint32_t*)qp, (uint32_t*)kp,
                                        scale_q, scale_k, scale_v, n4);

    cudaFuncSetAttribute(attn_kernel, cudaFuncAttributeMaxDynamicSharedMemorySize,
                         SMEM_ALL);
    attn_kernel<<<dim3(SQ / BM, NH), 256, SMEM_ALL>>>(scale_q, scale_k, scale_v,
                                                      descale_amax, out_scale, out);
}